// round 15
// baseline (speedup 1.0000x reference)
#include <cuda_runtime.h>
#include <math.h>
#include <stdint.h>

#define B_  2
#define S_  2048
#define D_  1024
#define H_  16
#define HD_ 64
#define M_  (B_*S_)
#define WPR 64               // mask bit-words per query row (S/32)
#define KU_ (D_/2)           // row stride in uint32 (bf16x2) = 512
#define WSZ (D_*D_/2)        // one weight matrix in uint32 = 524288 = 2^19

// Scratch (allocation-free), all bf16x2-packed hi/lo pairs
__device__ uint32_t g_Xh[M_*KU_],  g_Xl[M_*KU_];
__device__ uint32_t g_Wh[4*WSZ],   g_Wl[4*WSZ];       // Wq,Wk,Wv,Wo
__device__ uint32_t g_Oh[M_*KU_],  g_Ol[M_*KU_];
__device__ uint32_t g_Qh[B_*H_*S_*HD_/2], g_Ql[B_*H_*S_*HD_/2];
__device__ uint32_t g_Kh[B_*H_*S_*HD_/2], g_Kl[B_*H_*S_*HD_/2];
__device__ uint32_t g_Vh[B_*H_*S_*HD_/2], g_Vl[B_*H_*S_*HD_/2];
__device__ uint32_t g_mbits[B_*S_*WPR];
__device__ int      g_cnt[32];          // per-(b,qblock) completion counters

// ---------------------------------------------------------------------------
// helpers
// ---------------------------------------------------------------------------
__device__ __forceinline__ void mma_bf16(float* d, const uint32_t* a,
                                         uint32_t b0, uint32_t b1) {
    asm volatile(
        "mma.sync.aligned.m16n8k16.row.col.f32.bf16.bf16.f32 "
        "{%0,%1,%2,%3}, {%4,%5,%6,%7}, {%8,%9}, {%0,%1,%2,%3};"
        : "+f"(d[0]), "+f"(d[1]), "+f"(d[2]), "+f"(d[3])
        : "r"(a[0]), "r"(a[1]), "r"(a[2]), "r"(a[3]),
          "r"(b0), "r"(b1));
}

__device__ __forceinline__ void pack_hl(float v0, float v1,
                                        uint32_t& hi, uint32_t& lo) {
    asm("cvt.rn.bf16x2.f32 %0, %1, %2;" : "=r"(hi) : "f"(v1), "f"(v0));
    float h0 = __uint_as_float(hi << 16);
    float h1 = __uint_as_float(hi & 0xffff0000u);
    asm("cvt.rn.bf16x2.f32 %0, %1, %2;" : "=r"(lo) : "f"(v1 - h1), "f"(v0 - h0));
}

__device__ __forceinline__ void ldm4(uint32_t& r0, uint32_t& r1, uint32_t& r2,
                                     uint32_t& r3, uint32_t addr) {
    asm volatile("ldmatrix.sync.aligned.m8n8.x4.shared.b16 {%0,%1,%2,%3}, [%4];"
                 : "=r"(r0), "=r"(r1), "=r"(r2), "=r"(r3) : "r"(addr));
}
__device__ __forceinline__ void ldm4t(uint32_t& r0, uint32_t& r1, uint32_t& r2,
                                      uint32_t& r3, uint32_t addr) {
    asm volatile("ldmatrix.sync.aligned.m8n8.x4.trans.shared.b16 {%0,%1,%2,%3}, [%4];"
                 : "=r"(r0), "=r"(r1), "=r"(r2), "=r"(r3) : "r"(addr));
}

__device__ __forceinline__ void cp16(uint32_t dst, const void* src) {
    asm volatile("cp.async.cg.shared.global [%0], [%1], 16;" :: "r"(dst), "l"(src));
}
#define CP_COMMIT() asm volatile("cp.async.commit_group;")
template <int N>
__device__ __forceinline__ void cp_wait() {
    asm volatile("cp.async.wait_group %0;" :: "n"(N));
}

// ---------------------------------------------------------------------------
// fused prep: X split / W split / mask pack / counter reset, one launch
// ---------------------------------------------------------------------------
__global__ __launch_bounds__(256) void prep_all(
    const float* __restrict__ X,
    const float* __restrict__ wq, const float* __restrict__ wk,
    const float* __restrict__ wv, const float* __restrict__ wo,
    const int*   __restrict__ mask)
{
    int blk = blockIdx.x;
    if (blk == 0 && threadIdx.x < 32) g_cnt[threadIdx.x] = 0;
    if (blk < 1024) {
        int i0 = blk * 256 + threadIdx.x;
        for (int i = i0; i < M_ * KU_; i += 1024 * 256) {
            float2 v = ((const float2*)X)[i];
            uint32_t hi, lo;
            pack_hl(v.x, v.y, hi, lo);
            g_Xh[i] = hi; g_Xl[i] = lo;
        }
    } else if (blk < 2048) {
        int i0 = (blk - 1024) * 256 + threadIdx.x;
        for (int i = i0; i < 4 * WSZ; i += 1024 * 256) {
            int sel = i >> 19;
            int j   = i & (WSZ - 1);
            const float* src = (sel == 0) ? wq : (sel == 1) ? wk
                             : (sel == 2) ? wv : wo;
            float2 v = ((const float2*)src)[j];
            uint32_t hi, lo;
            pack_hl(v.x, v.y, hi, lo);
            g_Wh[i] = hi; g_Wl[i] = lo;
        }
    } else {
        int wrp  = (((blk - 2048) * 256) + threadIdx.x) >> 5;
        int lane = threadIdx.x & 31;
        int nw   = (512 * 256) >> 5;
        for (int w = wrp; w < B_ * S_ * WPR; w += nw) {
            int v = mask[(size_t)w * 32 + lane];
            uint32_t bits = __ballot_sync(0xffffffffu, v != 0);
            if (lane == 0) g_mbits[w] = bits;
        }
    }
}

// ---------------------------------------------------------------------------
// shared gemm mainloop (bf16x3, cp.async 2-stage).  outmode 0/1/2 -> Q/K/V,
// outmode 3 -> fp32 Yext. Used by the QKV kernel and the fused O-proj path.
// ---------------------------------------------------------------------------
#define LDU 20
#define ASZ (128*LDU)
#define GSTG 2
#define GNIT (KU_/16)

__device__ __forceinline__ void gemm_body(
    uint32_t* dsm, const uint32_t* Ah, const uint32_t* Al,
    const uint32_t* Bh, const uint32_t* Bl,
    int m0, int n0, int outmode, float* __restrict__ Yext)
{
    int t = threadIdx.x, wid = t >> 5, lane = t & 31;
    int wm = wid >> 2, wn = wid & 3;

    int lr  = t >> 1;
    int lcu = (t & 1) << 3;

    const uint32_t* pAh = Ah + (size_t)(m0 + lr) * KU_ + lcu;
    const uint32_t* pAl = Al + (size_t)(m0 + lr) * KU_ + lcu;
    const uint32_t* pBh = Bh + (size_t)(n0 + lr) * KU_ + lcu;
    const uint32_t* pBl = Bl + (size_t)(n0 + lr) * KU_ + lcu;

    uint32_t sbase = (uint32_t)__cvta_generic_to_shared(dsm);
    uint32_t dst0  = sbase + (uint32_t)(lr * LDU + lcu) * 4u;

    auto issue = [&](int buf, int ku) {
        uint32_t d = dst0 + (uint32_t)(buf * 4 * ASZ) * 4u;
        cp16(d,                  pAh + ku);
        cp16(d + 16,             pAh + ku + 4);
        cp16(d + ASZ*4,          pAl + ku);
        cp16(d + ASZ*4 + 16,     pAl + ku + 4);
        cp16(d + 2*ASZ*4,        pBh + ku);
        cp16(d + 2*ASZ*4 + 16,   pBh + ku + 4);
        cp16(d + 3*ASZ*4,        pBl + ku);
        cp16(d + 3*ASZ*4 + 16,   pBl + ku + 4);
    };

    float acc[4][4][4];
    #pragma unroll
    for (int i = 0; i < 4; i++)
        #pragma unroll
        for (int j = 0; j < 4; j++)
            #pragma unroll
            for (int q = 0; q < 4; q++) acc[i][j][q] = 0.f;

    int a_row = (lane & 15);
    int a_col = (lane >> 4) << 2;
    int b_row = ((lane >> 4) << 3) + (lane & 7);
    int b_col = ((lane >> 3) & 1) << 2;

    issue(0, 0); CP_COMMIT();

    for (int it = 0; it < GNIT; it++) {
        cp_wait<0>();
        __syncthreads();
        if (it + 1 < GNIT) { issue((it + 1) & 1, (it + 1) * 16); CP_COMMIT(); }

        const uint32_t* bAh = dsm + (it & 1) * 4 * ASZ;
        const uint32_t* bAl = bAh + ASZ;
        const uint32_t* bBh = bAh + 2 * ASZ;
        const uint32_t* bBl = bAh + 3 * ASZ;

        #pragma unroll
        for (int ch = 0; ch < 2; ch++) {
            int kc = ch << 3;
            uint32_t ah[4][4], al[4][4], bh[4][2], bl[4][2];

            #pragma unroll
            for (int mt = 0; mt < 4; mt++) {
                int off = ((wm << 6) + (mt << 4) + a_row) * LDU + kc + a_col;
                uint32_t addr_h = (uint32_t)__cvta_generic_to_shared(&bAh[off]);
                uint32_t addr_l = (uint32_t)__cvta_generic_to_shared(&bAl[off]);
                ldm4(ah[mt][0], ah[mt][1], ah[mt][2], ah[mt][3], addr_h);
                ldm4(al[mt][0], al[mt][1], al[mt][2], al[mt][3], addr_l);
            }
            #pragma unroll
            for (int np = 0; np < 2; np++) {
                int off = ((wn << 5) + (np << 4) + b_row) * LDU + kc + b_col;
                uint32_t addr_h = (uint32_t)__cvta_generic_to_shared(&bBh[off]);
                uint32_t addr_l = (uint32_t)__cvta_generic_to_shared(&bBl[off]);
                ldm4(bh[2*np][0], bh[2*np][1], bh[2*np+1][0], bh[2*np+1][1], addr_h);
                ldm4(bl[2*np][0], bl[2*np][1], bl[2*np+1][0], bl[2*np+1][1], addr_l);
            }

            #pragma unroll
            for (int mt = 0; mt < 4; mt++)
                #pragma unroll
                for (int nt = 0; nt < 4; nt++)
                    mma_bf16(acc[mt][nt], al[mt], bh[nt][0], bh[nt][1]);
            #pragma unroll
            for (int mt = 0; mt < 4; mt++)
                #pragma unroll
                for (int nt = 0; nt < 4; nt++)
                    mma_bf16(acc[mt][nt], ah[mt], bl[nt][0], bl[nt][1]);
            #pragma unroll
            for (int mt = 0; mt < 4; mt++)
                #pragma unroll
                for (int nt = 0; nt < 4; nt++)
                    mma_bf16(acc[mt][nt], ah[mt], bh[nt][0], bh[nt][1]);
        }
    }

    int lq = lane >> 2, lk = lane & 3;

    if (outmode == 3) {
        #pragma unroll
        for (int mt = 0; mt < 4; mt++) {
            int r = m0 + (wm << 6) + (mt << 4) + lq;
            #pragma unroll
            for (int nt = 0; nt < 4; nt++) {
                int c = n0 + (wn << 5) + (nt << 3) + (lk << 1);
                *(float2*)&Yext[(size_t)r * D_ + c] =
                    make_float2(acc[mt][nt][0], acc[mt][nt][1]);
                *(float2*)&Yext[(size_t)(r + 8) * D_ + c] =
                    make_float2(acc[mt][nt][2], acc[mt][nt][3]);
            }
        }
    } else {
        uint32_t* dh = (outmode == 0) ? g_Qh : (outmode == 1 ? g_Kh : g_Vh);
        uint32_t* dl = (outmode == 0) ? g_Ql : (outmode == 1 ? g_Kl : g_Vl);
        #pragma unroll
        for (int mt = 0; mt < 4; mt++) {
            int r = m0 + (wm << 6) + (mt << 4) + lq;
            #pragma unroll
            for (int nt = 0; nt < 4; nt++) {
                int c  = n0 + (wn << 5) + (nt << 3) + (lk << 1);
                int h  = c >> 6, hd = c & 63;
                uint32_t hi, lo;
                {
                    int b = r >> 11, s = r & (S_ - 1);
                    size_t idx = ((size_t)(((b << 4) | h) * S_ + s) << 5) + (hd >> 1);
                    pack_hl(acc[mt][nt][0], acc[mt][nt][1], hi, lo);
                    dh[idx] = hi; dl[idx] = lo;
                }
                {
                    int r2 = r + 8;
                    int b = r2 >> 11, s = r2 & (S_ - 1);
                    size_t idx = ((size_t)(((b << 4) | h) * S_ + s) << 5) + (hd >> 1);
                    pack_hl(acc[mt][nt][2], acc[mt][nt][3], hi, lo);
                    dh[idx] = hi; dl[idx] = lo;
                }
            }
        }
    }
}

// QKV projection kernel (grid z selects Wq/Wk/Wv)
__global__ __launch_bounds__(256, 2) void gemm_qkv()
{
    extern __shared__ __align__(16) uint32_t dsm[];
    int z = blockIdx.z;
    gemm_body(dsm, g_Xh, g_Xl,
              g_Wh + (size_t)z * WSZ, g_Wl + (size_t)z * WSZ,
              blockIdx.y << 7, blockIdx.x << 7, z, nullptr);
}

// ---------------------------------------------------------------------------
// FUSED attention + O-projection, one launch.
//   blocks [0,512)   : attention, HEAD-FASTEST order (group j = blk>>4 covers
//                      m-block j; the 16 blocks of a group are its 16 heads).
//                      Epilogue: fence + barrier + atomicAdd(g_cnt[j]).
//   blocks [512,768) : O-proj gemm; CTA oid: mblk = oid>>3, nblk = oid&7.
//                      Spins (acquire) until g_cnt[mblk]==16, then computes.
// Deadlock-free: all producers precede consumers in grid order and
// 256 consumers < 296 resident-CTA capacity.
// ---------------------------------------------------------------------------
#define VLDU 36
#define AVSZ (64*VLDU)
#define FMAX_ 16.0f

__global__ __launch_bounds__(256, 2) void fused_attn_oproj(float* __restrict__ out)
{
    extern __shared__ __align__(16) uint32_t fsm[];
    int blk = blockIdx.x;

    if (blk >= 512) {
        // ---------------- O-projection consumer ----------------
        int oid  = blk - 512;
        int mblk = oid >> 3, nblk = oid & 7;
        if (threadIdx.x == 0) {
            int v;
            do {
                asm volatile("ld.acquire.gpu.global.b32 %0, [%1];"
                             : "=r"(v) : "l"(&g_cnt[mblk]) : "memory");
                if (v < 16) __nanosleep(256);
            } while (v < 16);
        }
        __syncthreads();
        __threadfence();
        gemm_body(fsm, g_Oh, g_Ol,
                  g_Wh + (size_t)3 * WSZ, g_Wl + (size_t)3 * WSZ,
                  mblk << 7, nblk << 7, 3, out);
        return;
    }

    // ---------------- attention producer ----------------
    int grp = blk >> 4;                 // m-block index 0..31
    int h   = blk & 15;
    int b   = grp >> 4;
    int q0  = (grp & 15) << 7;
    int bh  = (b << 4) | h;

    int t = threadIdx.x, w = t >> 5, lane = t & 31;
    int r = lane >> 2, qt = lane & 3;
    int g8 = lane >> 3, l8 = lane & 7;
    int qw = q0 + (w << 4);

    const uint32_t* Kh = g_Kh + (size_t)bh * S_ * 32;
    const uint32_t* Kl = g_Kl + (size_t)bh * S_ * 32;
    const uint32_t* Vh = g_Vh + (size_t)bh * S_ * 32;
    const uint32_t* Vl = g_Vl + (size_t)bh * S_ * 32;
    const uint32_t* mbase = g_mbits + ((size_t)b * S_ + qw) * WPR;

    int lrow = t >> 2;
    int lcol = (t & 3) << 3;

    uint32_t sbase = (uint32_t)__cvta_generic_to_shared(fsm);
    uint32_t dst0  = sbase + (uint32_t)(lrow * VLDU + lcol) * 4u;

    auto issue = [&](int buf, int kv0) {
        size_t s0 = (size_t)(kv0 + lrow) * 32 + lcol;
        uint32_t d = dst0 + (uint32_t)(buf * 4 * AVSZ) * 4u;
        cp16(d,                   Kh + s0);
        cp16(d + 16,              Kh + s0 + 4);
        cp16(d + AVSZ*4,          Kl + s0);
        cp16(d + AVSZ*4 + 16,     Kl + s0 + 4);
        cp16(d + 2*AVSZ*4,        Vh + s0);
        cp16(d + 2*AVSZ*4 + 16,   Vh + s0 + 4);
        cp16(d + 3*AVSZ*4,        Vl + s0);
        cp16(d + 3*AVSZ*4 + 16,   Vl + s0 + 4);
    };

    uint32_t qah[4][4], qal[4][4];
    {
        const uint32_t* Qh = g_Qh + ((size_t)bh * S_ + qw) * 32;
        const uint32_t* Ql = g_Ql + ((size_t)bh * S_ + qw) * 32;
        #pragma unroll
        for (int ks = 0; ks < 4; ks++) {
            int i0 = r * 32 + ks * 8 + qt;
            qah[ks][0] = Qh[i0];           qah[ks][1] = Qh[i0 + 256];
            qah[ks][2] = Qh[i0 + 4];       qah[ks][3] = Qh[i0 + 260];
            qal[ks][0] = Ql[i0];           qal[ks][1] = Ql[i0 + 256];
            qal[ks][2] = Ql[i0 + 4];       qal[ks][3] = Ql[i0 + 260];
        }
    }

    float oacc[8][4];
    #pragma unroll
    for (int i = 0; i < 8; i++)
        #pragma unroll
        for (int j = 0; j < 4; j++) oacc[i][j] = 0.f;
    float li0 = 0.f, li1 = 0.f;

    issue(0, 0); CP_COMMIT();

    for (int it = 0; it < S_ / 64; it++) {
        int kv0 = it << 6;
        cp_wait<0>();
        __syncthreads();
        if (it + 1 < S_ / 64) issue((it + 1) & 1, kv0 + 64);
        CP_COMMIT();

        const uint32_t* bKh = fsm + (it & 1) * 4 * AVSZ;
        const uint32_t* bKl = bKh + AVSZ;
        const uint32_t* bVh = bKh + 2 * AVSZ;
        const uint32_t* bVl = bKh + 3 * AVSZ;

        float sacc[8][4];
        #pragma unroll
        for (int i = 0; i < 8; i++)
            #pragma unroll
            for (int j = 0; j < 4; j++) sacc[i][j] = 0.f;

        #pragma unroll
        for (int ks = 0; ks < 4; ks++) {
            #pragma unroll
            for (int ntp = 0; ntp < 4; ntp++) {
                int row = (ntp << 4) + ((g8 & 2) ? 8 : 0) + l8;
                int col = (ks << 3) + ((g8 & 1) ? 4 : 0);
                uint32_t ah = (uint32_t)__cvta_generic_to_shared(&bKh[row * VLDU + col]);
                uint32_t al = (uint32_t)__cvta_generic_to_shared(&bKl[row * VLDU + col]);
                uint32_t h0, h1, h2, h3, l0, l1, l2, l3;
                ldm4(h0, h1, h2, h3, ah);
                ldm4(l0, l1, l2, l3, al);
                mma_bf16(sacc[2*ntp],   qal[ks], h0, h1);
                mma_bf16(sacc[2*ntp+1], qal[ks], h2, h3);
                mma_bf16(sacc[2*ntp],   qah[ks], l0, l1);
                mma_bf16(sacc[2*ntp+1], qah[ks], l2, l3);
                mma_bf16(sacc[2*ntp],   qah[ks], h0, h1);
                mma_bf16(sacc[2*ntp+1], qah[ks], h2, h3);
            }
        }

        {
            const uint32_t* mb = mbase + (kv0 >> 5);
            uint32_t w0a = mb[(size_t)r * WPR];
            uint32_t w0b = mb[(size_t)r * WPR + 1];
            uint32_t w1a = mb[(size_t)(r + 8) * WPR];
            uint32_t w1b = mb[(size_t)(r + 8) * WPR + 1];
            #pragma unroll
            for (int nt = 0; nt < 8; nt++) {
                uint32_t wlo = (nt < 4) ? w0a : w0b;
                uint32_t whi = (nt < 4) ? w1a : w1b;
                int base = ((nt & 3) << 3) + (qt << 1);
                sacc[nt][0] = ((wlo >> base)       & 1) ? sacc[nt][0] * 0.125f : -1e-9f;
                sacc[nt][1] = ((wlo >> (base + 1)) & 1) ? sacc[nt][1] * 0.125f : -1e-9f;
                sacc[nt][2] = ((whi >> base)       & 1) ? sacc[nt][2] * 0.125f : -1e-9f;
                sacc[nt][3] = ((whi >> (base + 1)) & 1) ? sacc[nt][3] * 0.125f : -1e-9f;
            }
        }

        float rs0 = 0.f, rs1 = 0.f;
        #pragma unroll
        for (int nt = 0; nt < 8; nt++) {
            sacc[nt][0] = __expf(sacc[nt][0] - FMAX_);
            sacc[nt][1] = __expf(sacc[nt][1] - FMAX_);
            sacc[nt][2] = __expf(sacc[nt][2] - FMAX_);
            sacc[nt][3] = __expf(sacc[nt][3] - FMAX_);
            rs0 += sacc[nt][0] + sacc[nt][1];
            rs1 += sacc[nt][2] + sacc[nt][3];
        }
        rs0 += __shfl_xor_sync(0xffffffffu, rs0, 1);
        rs0 += __shfl_xor_sync(0xffffffffu, rs0, 2);
        rs1 += __shfl_xor_sync(0xffffffffu, rs1, 1);
        rs1 += __shfl_xor_sync(0xffffffffu, rs1, 2);
        li0 += rs0;
        li1 += rs1;

        uint32_t pah[4][4], pal[4][4];
        #pragma unroll
        for (int ks = 0; ks < 4; ks++) {
            pack_hl(sacc[2*ks][0],   sacc[2*ks][1],   pah[ks][0], pal[ks][0]);
            pack_hl(sacc[2*ks][2],   sacc[2*ks][3],   pah[ks][1], pal[ks][1]);
            pack_hl(sacc[2*ks+1][0], sacc[2*ks+1][1], pah[ks][2], pal[ks][2]);
            pack_hl(sacc[2*ks+1][2], sacc[2*ks+1][3], pah[ks][3], pal[ks][3]);
        }

        #pragma unroll
        for (int ks = 0; ks < 4; ks++) {
            #pragma unroll
            for (int ntp = 0; ntp < 4; ntp++) {
                int row = (ks << 4) + ((g8 & 1) ? 8 : 0) + l8;
                int col = (ntp << 3) + ((g8 & 2) ? 4 : 0);
                uint32_t ah = (uint32_t)__cvta_generic_to_shared(&bVh[row * VLDU + col]);
                uint32_t al = (uint32_t)__cvta_generic_to_shared(&bVl[row * VLDU + col]);
                uint32_t h0, h1, h2, h3, l0, l1, l2, l3;
                ldm4t(h0, h1, h2, h3, ah);
                ldm4t(l0, l1, l2, l3, al);
                mma_bf16(oacc[2*ntp],   pal[ks], h0, h1);
                mma_bf16(oacc[2*ntp+1], pal[ks], h2, h3);
                mma_bf16(oacc[2*ntp],   pah[ks], l0, l1);
                mma_bf16(oacc[2*ntp+1], pah[ks], l2, l3);
                mma_bf16(oacc[2*ntp],   pah[ks], h0, h1);
                mma_bf16(oacc[2*ntp+1], pah[ks], h2, h3);
            }
        }
    }

    // epilogue: normalize, pack to bf16 hi/lo O [m][d/2]
    float inv0 = 1.0f / li0, inv1 = 1.0f / li1;
    size_t rowbase = (size_t)b * S_ + qw;
    uint32_t* Oh = g_Oh + rowbase * KU_ + (h << 5);
    uint32_t* Ol = g_Ol + rowbase * KU_ + (h << 5);
    #pragma unroll
    for (int nt = 0; nt < 8; nt++) {
        int cu = (nt << 2) + qt;
        uint32_t hi, lo;
        pack_hl(oacc[nt][0] * inv0, oacc[nt][1] * inv0, hi, lo);
        Oh[(size_t)r * KU_ + cu] = hi;
        Ol[(size_t)r * KU_ + cu] = lo;
        pack_hl(oacc[nt][2] * inv1, oacc[nt][3] * inv1, hi, lo);
        Oh[(size_t)(r + 8) * KU_ + cu] = hi;
        Ol[(size_t)(r + 8) * KU_ + cu] = lo;
    }

    // signal completion of this head's slice of m-block `grp`
    __threadfence();
    __syncthreads();
    if (threadIdx.x == 0) atomicAdd(&g_cnt[grp], 1);
}

// ---------------------------------------------------------------------------
extern "C" void kernel_launch(void* const* d_in, const int* in_sizes, int n_in,
                              void* d_out, int out_size)
{
    const float* X    = (const float*)d_in[0];
    const int*   mask = (const int*)d_in[1];
    const float* Wq   = (const float*)d_in[2];
    const float* Wk   = (const float*)d_in[3];
    const float* Wv   = (const float*)d_in[4];
    const float* Wo   = (const float*)d_in[5];
    float* out = (float*)d_out;

    size_t gsmem = (size_t)GSTG * 4 * ASZ * sizeof(uint32_t);   // 81920 B
    cudaFuncSetAttribute(gemm_qkv,
                         cudaFuncAttributeMaxDynamicSharedMemorySize, (int)gsmem);
    cudaFuncSetAttribute(fused_attn_oproj,
                         cudaFuncAttributeMaxDynamicSharedMemorySize, (int)gsmem);

    prep_all<<<2560, 256>>>(X, Wq, Wk, Wv, Wo, mask);
    gemm_qkv<<<dim3(D_/128, M_/128, 3), 256, gsmem>>>();
    fused_attn_oproj<<<768, 256, gsmem>>>(out);
}

// round 16
// speedup vs baseline: 1.0362x; 1.0362x over previous
#include <cuda_runtime.h>
#include <math.h>
#include <stdint.h>

#define B_  2
#define S_  2048
#define D_  1024
#define H_  16
#define HD_ 64
#define M_  (B_*S_)
#define WPR 64               // mask bit-words per query row (S/32)
#define KU_ (D_/2)           // row stride in uint32 (bf16x2) = 512
#define WSZ (D_*D_/2)        // one weight matrix in uint32 = 524288

// Scratch (allocation-free), all bf16x2-packed hi/lo pairs
__device__ uint32_t g_Xh[M_*KU_],  g_Xl[M_*KU_];
__device__ uint32_t g_Wh[4*WSZ],   g_Wl[4*WSZ];       // Wq,Wk,Wv,Wo
__device__ uint32_t g_Oh[M_*KU_],  g_Ol[M_*KU_];
__device__ uint32_t g_Qh[B_*H_*S_*HD_/2], g_Ql[B_*H_*S_*HD_/2];
__device__ uint32_t g_Kh[B_*H_*S_*HD_/2], g_Kl[B_*H_*S_*HD_/2];
__device__ uint32_t g_Vh[B_*H_*S_*HD_/2], g_Vl[B_*H_*S_*HD_/2];
__device__ uint32_t g_mbits[B_*S_*WPR];

// ---------------------------------------------------------------------------
// helpers
// ---------------------------------------------------------------------------
__device__ __forceinline__ void mma_bf16(float* d, const uint32_t* a,
                                         uint32_t b0, uint32_t b1) {
    asm volatile(
        "mma.sync.aligned.m16n8k16.row.col.f32.bf16.bf16.f32 "
        "{%0,%1,%2,%3}, {%4,%5,%6,%7}, {%8,%9}, {%0,%1,%2,%3};"
        : "+f"(d[0]), "+f"(d[1]), "+f"(d[2]), "+f"(d[3])
        : "r"(a[0]), "r"(a[1]), "r"(a[2]), "r"(a[3]),
          "r"(b0), "r"(b1));
}

__device__ __forceinline__ void pack_hl(float v0, float v1,
                                        uint32_t& hi, uint32_t& lo) {
    asm("cvt.rn.bf16x2.f32 %0, %1, %2;" : "=r"(hi) : "f"(v1), "f"(v0));
    float h0 = __uint_as_float(hi << 16);
    float h1 = __uint_as_float(hi & 0xffff0000u);
    asm("cvt.rn.bf16x2.f32 %0, %1, %2;" : "=r"(lo) : "f"(v1 - h1), "f"(v0 - h0));
}

__device__ __forceinline__ void ldm4(uint32_t& r0, uint32_t& r1, uint32_t& r2,
                                     uint32_t& r3, uint32_t addr) {
    asm volatile("ldmatrix.sync.aligned.m8n8.x4.shared.b16 {%0,%1,%2,%3}, [%4];"
                 : "=r"(r0), "=r"(r1), "=r"(r2), "=r"(r3) : "r"(addr));
}
__device__ __forceinline__ void ldm4t(uint32_t& r0, uint32_t& r1, uint32_t& r2,
                                      uint32_t& r3, uint32_t addr) {
    asm volatile("ldmatrix.sync.aligned.m8n8.x4.trans.shared.b16 {%0,%1,%2,%3}, [%4];"
                 : "=r"(r0), "=r"(r1), "=r"(r2), "=r"(r3) : "r"(addr));
}

__device__ __forceinline__ void cp16(uint32_t dst, const void* src) {
    asm volatile("cp.async.cg.shared.global [%0], [%1], 16;" :: "r"(dst), "l"(src));
}
#define CP_COMMIT() asm volatile("cp.async.commit_group;")
template <int N>
__device__ __forceinline__ void cp_wait() {
    asm volatile("cp.async.wait_group %0;" :: "n"(N));
}

// ---------------------------------------------------------------------------
// fp32 -> bf16 hi/lo split: X (one launch) and 4 weights (one launch, grid.y)
// ---------------------------------------------------------------------------
__global__ void prep_x(const float* __restrict__ src) {
    int i0 = blockIdx.x * blockDim.x + threadIdx.x;
    int stride = gridDim.x * blockDim.x;
    for (int i = i0; i < M_ * KU_; i += stride) {
        float2 v = ((const float2*)src)[i];
        uint32_t hi, lo;
        pack_hl(v.x, v.y, hi, lo);
        g_Xh[i] = hi; g_Xl[i] = lo;
    }
}

__global__ void prep_w(const float* __restrict__ wq, const float* __restrict__ wk,
                       const float* __restrict__ wv, const float* __restrict__ wo) {
    int sel = blockIdx.y;
    const float* src = (sel == 0) ? wq : (sel == 1) ? wk : (sel == 2) ? wv : wo;
    uint32_t* dh = g_Wh + (size_t)sel * WSZ;
    uint32_t* dl = g_Wl + (size_t)sel * WSZ;
    int i0 = blockIdx.x * blockDim.x + threadIdx.x;
    int stride = gridDim.x * blockDim.x;
    for (int i = i0; i < WSZ; i += stride) {
        float2 v = ((const float2*)src)[i];
        uint32_t hi, lo;
        pack_hl(v.x, v.y, hi, lo);
        dh[i] = hi; dl[i] = lo;
    }
}

// ---------------------------------------------------------------------------
// mask bit-packing
// ---------------------------------------------------------------------------
__global__ void pack_mask(const int* __restrict__ mask) {
    int warp  = (blockIdx.x * blockDim.x + threadIdx.x) >> 5;
    int lane  = threadIdx.x & 31;
    int nwarp = (gridDim.x * blockDim.x) >> 5;
    for (int w = warp; w < B_ * S_ * WPR; w += nwarp) {
        int v = mask[(size_t)w * 32 + lane];
        uint32_t bits = __ballot_sync(0xffffffffu, v != 0);
        if (lane == 0) g_mbits[w] = bits;
    }
}

// ---------------------------------------------------------------------------
// bf16x3 tensor-core GEMM, cp.async 2-stage pipeline, 2 CTAs/SM.
// BM=BN=128, BK=32 (16 uints), 256 thr = 8 warps (2x4), warp tile 64x32.
// Term-major mma issue. modep==0: A=g_X, B=W[z] -> Q/K/V; modep==3 -> fp32.
// ---------------------------------------------------------------------------
#define LDU 20                 // smem row stride (uints), conflict-free ldmatrix
#define ASZ (128*LDU)          // one operand tile (uints)
#define GSTG 2                 // pipeline stages (80KB -> 2 CTAs/SM)
#define GNIT (KU_/16)          // 32 mainloop iters

__global__ __launch_bounds__(256, 2) void gemm_bf16(float* __restrict__ Yext,
                                                    int modep)
{
    extern __shared__ __align__(16) uint32_t dsm[];   // GSTG stages x 4 tiles

    int z = blockIdx.z;
    int outmode = (modep == 3) ? 3 : z;

    const uint32_t *Ah, *Al, *Bh, *Bl;
    if (modep == 3) {
        Ah = g_Oh; Al = g_Ol;
        Bh = g_Wh + (size_t)3 * WSZ; Bl = g_Wl + (size_t)3 * WSZ;
    } else {
        Ah = g_Xh; Al = g_Xl;
        Bh = g_Wh + (size_t)z * WSZ; Bl = g_Wl + (size_t)z * WSZ;
    }

    int t = threadIdx.x, wid = t >> 5, lane = t & 31;
    int wm = wid >> 2, wn = wid & 3;
    int m0 = blockIdx.y << 7, n0 = blockIdx.x << 7;

    int lr  = t >> 1;            // 0..127
    int lcu = (t & 1) << 3;      // 0 or 8

    const uint32_t* pAh = Ah + (size_t)(m0 + lr) * KU_ + lcu;
    const uint32_t* pAl = Al + (size_t)(m0 + lr) * KU_ + lcu;
    const uint32_t* pBh = Bh + (size_t)(n0 + lr) * KU_ + lcu;
    const uint32_t* pBl = Bl + (size_t)(n0 + lr) * KU_ + lcu;

    uint32_t sbase = (uint32_t)__cvta_generic_to_shared(dsm);
    uint32_t dst0  = sbase + (uint32_t)(lr * LDU + lcu) * 4u;

    auto issue = [&](int buf, int ku) {
        uint32_t d = dst0 + (uint32_t)(buf * 4 * ASZ) * 4u;
        cp16(d,                  pAh + ku);
        cp16(d + 16,             pAh + ku + 4);
        cp16(d + ASZ*4,          pAl + ku);
        cp16(d + ASZ*4 + 16,     pAl + ku + 4);
        cp16(d + 2*ASZ*4,        pBh + ku);
        cp16(d + 2*ASZ*4 + 16,   pBh + ku + 4);
        cp16(d + 3*ASZ*4,        pBl + ku);
        cp16(d + 3*ASZ*4 + 16,   pBl + ku + 4);
    };

    float acc[4][4][4];
    #pragma unroll
    for (int i = 0; i < 4; i++)
        #pragma unroll
        for (int j = 0; j < 4; j++)
            #pragma unroll
            for (int q = 0; q < 4; q++) acc[i][j][q] = 0.f;

    int a_row = (lane & 15);
    int a_col = (lane >> 4) << 2;
    int b_row = ((lane >> 4) << 3) + (lane & 7);
    int b_col = ((lane >> 3) & 1) << 2;

    issue(0, 0); CP_COMMIT();

    for (int it = 0; it < GNIT; it++) {
        cp_wait<0>();
        __syncthreads();
        if (it + 1 < GNIT) { issue((it + 1) & 1, (it + 1) * 16); CP_COMMIT(); }

        const uint32_t* bAh = dsm + (it & 1) * 4 * ASZ;
        const uint32_t* bAl = bAh + ASZ;
        const uint32_t* bBh = bAh + 2 * ASZ;
        const uint32_t* bBl = bAh + 3 * ASZ;

        #pragma unroll
        for (int ch = 0; ch < 2; ch++) {
            int kc = ch << 3;
            uint32_t ah[4][4], al[4][4], bh[4][2], bl[4][2];

            #pragma unroll
            for (int mt = 0; mt < 4; mt++) {
                int off = ((wm << 6) + (mt << 4) + a_row) * LDU + kc + a_col;
                uint32_t addr_h = (uint32_t)__cvta_generic_to_shared(&bAh[off]);
                uint32_t addr_l = (uint32_t)__cvta_generic_to_shared(&bAl[off]);
                ldm4(ah[mt][0], ah[mt][1], ah[mt][2], ah[mt][3], addr_h);
                ldm4(al[mt][0], al[mt][1], al[mt][2], al[mt][3], addr_l);
            }
            #pragma unroll
            for (int np = 0; np < 2; np++) {
                int off = ((wn << 5) + (np << 4) + b_row) * LDU + kc + b_col;
                uint32_t addr_h = (uint32_t)__cvta_generic_to_shared(&bBh[off]);
                uint32_t addr_l = (uint32_t)__cvta_generic_to_shared(&bBl[off]);
                ldm4(bh[2*np][0], bh[2*np][1], bh[2*np+1][0], bh[2*np+1][1], addr_h);
                ldm4(bl[2*np][0], bl[2*np][1], bl[2*np+1][0], bl[2*np+1][1], addr_l);
            }

            #pragma unroll
            for (int mt = 0; mt < 4; mt++)
                #pragma unroll
                for (int nt = 0; nt < 4; nt++)
                    mma_bf16(acc[mt][nt], al[mt], bh[nt][0], bh[nt][1]);
            #pragma unroll
            for (int mt = 0; mt < 4; mt++)
                #pragma unroll
                for (int nt = 0; nt < 4; nt++)
                    mma_bf16(acc[mt][nt], ah[mt], bl[nt][0], bl[nt][1]);
            #pragma unroll
            for (int mt = 0; mt < 4; mt++)
                #pragma unroll
                for (int nt = 0; nt < 4; nt++)
                    mma_bf16(acc[mt][nt], ah[mt], bh[nt][0], bh[nt][1]);
        }
    }

    int lq = lane >> 2, lk = lane & 3;

    if (outmode == 3) {
        #pragma unroll
        for (int mt = 0; mt < 4; mt++) {
            int r = m0 + (wm << 6) + (mt << 4) + lq;
            #pragma unroll
            for (int nt = 0; nt < 4; nt++) {
                int c = n0 + (wn << 5) + (nt << 3) + (lk << 1);
                *(float2*)&Yext[(size_t)r * D_ + c] =
                    make_float2(acc[mt][nt][0], acc[mt][nt][1]);
                *(float2*)&Yext[(size_t)(r + 8) * D_ + c] =
                    make_float2(acc[mt][nt][2], acc[mt][nt][3]);
            }
        }
    } else {
        uint32_t* dh = (outmode == 0) ? g_Qh : (outmode == 1 ? g_Kh : g_Vh);
        uint32_t* dl = (outmode == 0) ? g_Ql : (outmode == 1 ? g_Kl : g_Vl);
        #pragma unroll
        for (int mt = 0; mt < 4; mt++) {
            int r = m0 + (wm << 6) + (mt << 4) + lq;
            #pragma unroll
            for (int nt = 0; nt < 4; nt++) {
                int c  = n0 + (wn << 5) + (nt << 3) + (lk << 1);
                int h  = c >> 6, hd = c & 63;
                uint32_t hi, lo;
                {
                    int b = r >> 11, s = r & (S_ - 1);
                    size_t idx = ((size_t)(((b << 4) | h) * S_ + s) << 5) + (hd >> 1);
                    pack_hl(acc[mt][nt][0], acc[mt][nt][1], hi, lo);
                    dh[idx] = hi; dl[idx] = lo;
                }
                {
                    int r2 = r + 8;
                    int b = r2 >> 11, s = r2 & (S_ - 1);
                    size_t idx = ((size_t)(((b << 4) | h) * S_ + s) << 5) + (hd >> 1);
                    pack_hl(acc[mt][nt][2], acc[mt][nt][3], hi, lo);
                    dh[idx] = hi; dl[idx] = lo;
                }
            }
        }
    }
}

// ---------------------------------------------------------------------------
// Tensor-core flash attention (bf16x3), cp.async 3-STAGE pipeline, 2 CTAs/SM.
// 3 stages x 36864B = 110592B; 2 CTAs = 221184B < 228KB/SM.
// cp_wait<1> keeps one tile of load slack to absorb L2 latency spikes.
// Fixed-shift softmax (M=16). Masked scores = -1e-9f exact after *0.125.
// ---------------------------------------------------------------------------
#define VLDU 36
#define AVSZ (64*VLDU)        // one K/V tile (uints)
#define ASTG 3                // attention pipeline stages
#define FMAX_ 16.0f           // fixed softmax shift

__global__ __launch_bounds__(256, 2) void attn_tc()
{
    extern __shared__ __align__(16) uint32_t asm_[];  // ASTG stages x 4 tiles

    int t = threadIdx.x, w = t >> 5, lane = t & 31;
    int r = lane >> 2, qt = lane & 3;
    int g8 = lane >> 3, l8 = lane & 7;

    int bh = blockIdx.y, b = bh >> 4, h = bh & 15;
    int q0 = blockIdx.x << 7;
    int qw = q0 + (w << 4);

    const uint32_t* Kh = g_Kh + (size_t)bh * S_ * 32;
    const uint32_t* Kl = g_Kl + (size_t)bh * S_ * 32;
    const uint32_t* Vh = g_Vh + (size_t)bh * S_ * 32;
    const uint32_t* Vl = g_Vl + (size_t)bh * S_ * 32;
    const uint32_t* mbase = g_mbits + ((size_t)b * S_ + qw) * WPR;

    int lrow = t >> 2;           // 0..63
    int lcol = (t & 3) << 3;     // 0,8,16,24

    uint32_t sbase = (uint32_t)__cvta_generic_to_shared(asm_);
    uint32_t dst0  = sbase + (uint32_t)(lrow * VLDU + lcol) * 4u;

    auto issue = [&](int buf, int kv0) {
        size_t s0 = (size_t)(kv0 + lrow) * 32 + lcol;
        uint32_t d = dst0 + (uint32_t)(buf * 4 * AVSZ) * 4u;
        cp16(d,                   Kh + s0);
        cp16(d + 16,              Kh + s0 + 4);
        cp16(d + AVSZ*4,          Kl + s0);
        cp16(d + AVSZ*4 + 16,     Kl + s0 + 4);
        cp16(d + 2*AVSZ*4,        Vh + s0);
        cp16(d + 2*AVSZ*4 + 16,   Vh + s0 + 4);
        cp16(d + 3*AVSZ*4,        Vl + s0);
        cp16(d + 3*AVSZ*4 + 16,   Vl + s0 + 4);
    };

    // Q A-fragments (hi/lo) once
    uint32_t qah[4][4], qal[4][4];
    {
        const uint32_t* Qh = g_Qh + ((size_t)bh * S_ + qw) * 32;
        const uint32_t* Ql = g_Ql + ((size_t)bh * S_ + qw) * 32;
        #pragma unroll
        for (int ks = 0; ks < 4; ks++) {
            int i0 = r * 32 + ks * 8 + qt;
            qah[ks][0] = Qh[i0];           qah[ks][1] = Qh[i0 + 256];
            qah[ks][2] = Qh[i0 + 4];       qah[ks][3] = Qh[i0 + 260];
            qal[ks][0] = Ql[i0];           qal[ks][1] = Ql[i0 + 256];
            qal[ks][2] = Ql[i0 + 4];       qal[ks][3] = Ql[i0 + 260];
        }
    }

    float oacc[8][4];
    #pragma unroll
    for (int i = 0; i < 8; i++)
        #pragma unroll
        for (int j = 0; j < 4; j++) oacc[i][j] = 0.f;
    float li0 = 0.f, li1 = 0.f;

    // prologue: stages 0,1
    issue(0, 0);  CP_COMMIT();
    issue(1, 64); CP_COMMIT();

    const int NIT = S_ / 64;     // 32
    for (int it = 0; it < NIT; it++) {
        cp_wait<ASTG - 2>();     // stage `it` resident, one group may remain
        __syncthreads();         // WAR: all warps done with buffer (it+2)%3
        if (it + 2 < NIT) { issue((it + 2) % ASTG, (it + 2) << 6); CP_COMMIT(); }

        const uint32_t* bKh = asm_ + (it % ASTG) * 4 * AVSZ;
        const uint32_t* bKl = bKh + AVSZ;
        const uint32_t* bVh = bKh + 2 * AVSZ;
        const uint32_t* bVl = bKh + 3 * AVSZ;

        float sacc[8][4];
        #pragma unroll
        for (int i = 0; i < 8; i++)
            #pragma unroll
            for (int j = 0; j < 4; j++) sacc[i][j] = 0.f;

        #pragma unroll
        for (int ks = 0; ks < 4; ks++) {
            #pragma unroll
            for (int ntp = 0; ntp < 4; ntp++) {
                int row = (ntp << 4) + ((g8 & 2) ? 8 : 0) + l8;
                int col = (ks << 3) + ((g8 & 1) ? 4 : 0);
                uint32_t ah = (uint32_t)__cvta_generic_to_shared(&bKh[row * VLDU + col]);
                uint32_t al = (uint32_t)__cvta_generic_to_shared(&bKl[row * VLDU + col]);
                uint32_t h0, h1, h2, h3, l0, l1, l2, l3;
                ldm4(h0, h1, h2, h3, ah);
                ldm4(l0, l1, l2, l3, al);
                mma_bf16(sacc[2*ntp],   qal[ks], h0, h1);
                mma_bf16(sacc[2*ntp+1], qal[ks], h2, h3);
                mma_bf16(sacc[2*ntp],   qah[ks], l0, l1);
                mma_bf16(sacc[2*ntp+1], qah[ks], l2, l3);
                mma_bf16(sacc[2*ntp],   qah[ks], h0, h1);
                mma_bf16(sacc[2*ntp+1], qah[ks], h2, h3);
            }
        }

        {
            int kv0 = it << 6;
            const uint32_t* mb = mbase + (kv0 >> 5);
            uint32_t w0a = mb[(size_t)r * WPR];
            uint32_t w0b = mb[(size_t)r * WPR + 1];
            uint32_t w1a = mb[(size_t)(r + 8) * WPR];
            uint32_t w1b = mb[(size_t)(r + 8) * WPR + 1];
            #pragma unroll
            for (int nt = 0; nt < 8; nt++) {
                uint32_t wlo = (nt < 4) ? w0a : w0b;
                uint32_t whi = (nt < 4) ? w1a : w1b;
                int base = ((nt & 3) << 3) + (qt << 1);
                sacc[nt][0] = ((wlo >> base)       & 1) ? sacc[nt][0] * 0.125f : -1e-9f;
                sacc[nt][1] = ((wlo >> (base + 1)) & 1) ? sacc[nt][1] * 0.125f : -1e-9f;
                sacc[nt][2] = ((whi >> base)       & 1) ? sacc[nt][2] * 0.125f : -1e-9f;
                sacc[nt][3] = ((whi >> (base + 1)) & 1) ? sacc[nt][3] * 0.125f : -1e-9f;
            }
        }

        float rs0 = 0.f, rs1 = 0.f;
        #pragma unroll
        for (int nt = 0; nt < 8; nt++) {
            sacc[nt][0] = __expf(sacc[nt][0] - FMAX_);
            sacc[nt][1] = __expf(sacc[nt][1] - FMAX_);
            sacc[nt][2] = __expf(sacc[nt][2] - FMAX_);
            sacc[nt][3] = __expf(sacc[nt][3] - FMAX_);
            rs0 += sacc[nt][0] + sacc[nt][1];
            rs1 += sacc[nt][2] + sacc[nt][3];
        }
        rs0 += __shfl_xor_sync(0xffffffffu, rs0, 1);
        rs0 += __shfl_xor_sync(0xffffffffu, rs0, 2);
        rs1 += __shfl_xor_sync(0xffffffffu, rs1, 1);
        rs1 += __shfl_xor_sync(0xffffffffu, rs1, 2);
        li0 += rs0;
        li1 += rs1;

        uint32_t pah[4][4], pal[4][4];
        #pragma unroll
        for (int ks = 0; ks < 4; ks++) {
            pack_hl(sacc[2*ks][0],   sacc[2*ks][1],   pah[ks][0], pal[ks][0]);
            pack_hl(sacc[2*ks][2],   sacc[2*ks][3],   pah[ks][1], pal[ks][1]);
            pack_hl(sacc[2*ks+1][0], sacc[2*ks+1][1], pah[ks][2], pal[ks][2]);
            pack_hl(sacc[2*ks+1][2], sacc[2*ks+1][3], pah[ks][3], pal[ks][3]);
        }

        #pragma unroll
        for (int ks = 0; ks < 4; ks++) {
            #pragma unroll
            for (int ntp = 0; ntp < 4; ntp++) {
                int row = (ks << 4) + ((g8 & 1) ? 8 : 0) + l8;
                int col = (ntp << 3) + ((g8 & 2) ? 4 : 0);
                uint32_t ah = (uint32_t)__cvta_generic_to_shared(&bVh[row * VLDU + col]);
                uint32_t al = (uint32_t)__cvta_generic_to_shared(&bVl[row * VLDU + col]);
                uint32_t h0, h1, h2, h3, l0, l1, l2, l3;
                ldm4t(h0, h1, h2, h3, ah);
                ldm4t(l0, l1, l2, l3, al);
                mma_bf16(oacc[2*ntp],   pal[ks], h0, h1);
                mma_bf16(oacc[2*ntp+1], pal[ks], h2, h3);
                mma_bf16(oacc[2*ntp],   pah[ks], l0, l1);
                mma_bf16(oacc[2*ntp+1], pah[ks], l2, l3);
                mma_bf16(oacc[2*ntp],   pah[ks], h0, h1);
                mma_bf16(oacc[2*ntp+1], pah[ks], h2, h3);
            }
        }
    }

    // epilogue: normalize, pack to bf16 hi/lo O [m][d/2]
    float inv0 = 1.0f / li0, inv1 = 1.0f / li1;
    size_t rowbase = (size_t)b * S_ + qw;
    uint32_t* Oh = g_Oh + rowbase * KU_ + (h << 5);
    uint32_t* Ol = g_Ol + rowbase * KU_ + (h << 5);
    #pragma unroll
    for (int nt = 0; nt < 8; nt++) {
        int cu = (nt << 2) + qt;
        uint32_t hi, lo;
        pack_hl(oacc[nt][0] * inv0, oacc[nt][1] * inv0, hi, lo);
        Oh[(size_t)r * KU_ + cu] = hi;
        Ol[(size_t)r * KU_ + cu] = lo;
        pack_hl(oacc[nt][2] * inv1, oacc[nt][3] * inv1, hi, lo);
        Oh[(size_t)(r + 8) * KU_ + cu] = hi;
        Ol[(size_t)(r + 8) * KU_ + cu] = lo;
    }
}

// ---------------------------------------------------------------------------
extern "C" void kernel_launch(void* const* d_in, const int* in_sizes, int n_in,
                              void* d_out, int out_size)
{
    const float* X    = (const float*)d_in[0];
    const int*   mask = (const int*)d_in[1];
    const float* Wq   = (const float*)d_in[2];
    const float* Wk   = (const float*)d_in[3];
    const float* Wv   = (const float*)d_in[4];
    const float* Wo   = (const float*)d_in[5];
    float* out = (float*)d_out;

    size_t gsmem  = (size_t)GSTG * 4 * ASZ * sizeof(uint32_t);    // 81920 B
    size_t atsmem = (size_t)ASTG * 4 * AVSZ * sizeof(uint32_t);   // 110592 B
    cudaFuncSetAttribute(gemm_bf16,
                         cudaFuncAttributeMaxDynamicSharedMemorySize, (int)gsmem);
    cudaFuncSetAttribute(attn_tc,
                         cudaFuncAttributeMaxDynamicSharedMemorySize, (int)atsmem);

    pack_mask<<<2048, 256>>>(mask);
    prep_x<<<1184, 256>>>(X);
    prep_w<<<dim3(296, 4), 256>>>(Wq, Wk, Wv, Wo);

    gemm_bf16<<<dim3(D_/128, M_/128, 3), 256, gsmem>>>(nullptr, 0);
    attn_tc<<<dim3(S_ / 128, B_ * H_), 256, atsmem>>>();
    gemm_bf16<<<dim3(D_/128, M_/128, 1), 256, gsmem>>>(out, 3);
}

// round 17
// speedup vs baseline: 1.0629x; 1.0257x over previous
#include <cuda_runtime.h>
#include <math.h>
#include <stdint.h>

#define B_  2
#define S_  2048
#define D_  1024
#define H_  16
#define HD_ 64
#define M_  (B_*S_)
#define WPR 64               // mask bit-words per query row (S/32)
#define KU_ (D_/2)           // row stride in uint32 (bf16x2) = 512
#define WSZ (D_*D_/2)        // one weight matrix in uint32 = 524288 = 2^19
#define NPAIR 2097152        // M_*KU_ = 4*WSZ (pairs per prep half)

// Scratch (allocation-free), all bf16x2-packed hi/lo pairs
__device__ uint32_t g_Xh[M_*KU_],  g_Xl[M_*KU_];
__device__ uint32_t g_Wh[4*WSZ],   g_Wl[4*WSZ];       // Wq,Wk,Wv,Wo
__device__ uint32_t g_Oh[M_*KU_],  g_Ol[M_*KU_];
__device__ uint32_t g_Qh[B_*H_*S_*HD_/2], g_Ql[B_*H_*S_*HD_/2];
__device__ uint32_t g_Kh[B_*H_*S_*HD_/2], g_Kl[B_*H_*S_*HD_/2];
__device__ uint32_t g_Vh[B_*H_*S_*HD_/2], g_Vl[B_*H_*S_*HD_/2];
__device__ uint32_t g_mbits[B_*S_*WPR];

// ---------------------------------------------------------------------------
// helpers
// ---------------------------------------------------------------------------
__device__ __forceinline__ void mma_bf16(float* d, const uint32_t* a,
                                         uint32_t b0, uint32_t b1) {
    asm volatile(
        "mma.sync.aligned.m16n8k16.row.col.f32.bf16.bf16.f32 "
        "{%0,%1,%2,%3}, {%4,%5,%6,%7}, {%8,%9}, {%0,%1,%2,%3};"
        : "+f"(d[0]), "+f"(d[1]), "+f"(d[2]), "+f"(d[3])
        : "r"(a[0]), "r"(a[1]), "r"(a[2]), "r"(a[3]),
          "r"(b0), "r"(b1));
}

__device__ __forceinline__ void pack_hl(float v0, float v1,
                                        uint32_t& hi, uint32_t& lo) {
    asm("cvt.rn.bf16x2.f32 %0, %1, %2;" : "=r"(hi) : "f"(v1), "f"(v0));
    float h0 = __uint_as_float(hi << 16);
    float h1 = __uint_as_float(hi & 0xffff0000u);
    asm("cvt.rn.bf16x2.f32 %0, %1, %2;" : "=r"(lo) : "f"(v1 - h1), "f"(v0 - h0));
}

__device__ __forceinline__ void ldm4(uint32_t& r0, uint32_t& r1, uint32_t& r2,
                                     uint32_t& r3, uint32_t addr) {
    asm volatile("ldmatrix.sync.aligned.m8n8.x4.shared.b16 {%0,%1,%2,%3}, [%4];"
                 : "=r"(r0), "=r"(r1), "=r"(r2), "=r"(r3) : "r"(addr));
}
__device__ __forceinline__ void ldm4t(uint32_t& r0, uint32_t& r1, uint32_t& r2,
                                      uint32_t& r3, uint32_t addr) {
    asm volatile("ldmatrix.sync.aligned.m8n8.x4.trans.shared.b16 {%0,%1,%2,%3}, [%4];"
                 : "=r"(r0), "=r"(r1), "=r"(r2), "=r"(r3) : "r"(addr));
}

__device__ __forceinline__ void cp16(uint32_t dst, const void* src) {
    asm volatile("cp.async.cg.shared.global [%0], [%1], 16;" :: "r"(dst), "l"(src));
}
#define CP_COMMIT() asm volatile("cp.async.commit_group;")
template <int N>
__device__ __forceinline__ void cp_wait() {
    asm volatile("cp.async.wait_group %0;" :: "n"(N));
}

// ---------------------------------------------------------------------------
// fused + coarsened prep: blocks [0,1024) split X, [1024,2048) split weights.
// Exact division: each thread handles 8 independent pairs (unrolled -> MLP~8).
// ---------------------------------------------------------------------------
__global__ __launch_bounds__(256) void prep_xw(
    const float* __restrict__ X,
    const float* __restrict__ wq, const float* __restrict__ wk,
    const float* __restrict__ wv, const float* __restrict__ wo)
{
    int blk = blockIdx.x, t = threadIdx.x;
    if (blk < 1024) {
        int base = blk * 256 + t;
        #pragma unroll
        for (int k = 0; k < 8; k++) {
            int i = base + k * (1024 * 256);
            float2 v = ((const float2*)X)[i];
            uint32_t hi, lo;
            pack_hl(v.x, v.y, hi, lo);
            g_Xh[i] = hi; g_Xl[i] = lo;
        }
    } else {
        int base = (blk - 1024) * 256 + t;
        #pragma unroll
        for (int k = 0; k < 8; k++) {
            int i = base + k * (1024 * 256);
            int sel = i >> 19;
            int j   = i & (WSZ - 1);
            const float* src = (sel == 0) ? wq : (sel == 1) ? wk
                             : (sel == 2) ? wv : wo;
            float2 v = ((const float2*)src)[j];
            uint32_t hi, lo;
            pack_hl(v.x, v.y, hi, lo);
            g_Wh[i] = hi; g_Wl[i] = lo;
        }
    }
}

// ---------------------------------------------------------------------------
// bf16x3 tensor-core GEMM, cp.async 2-stage pipeline, 2 CTAs/SM.
// BM=BN=128, BK=32 (16 uints), 256 thr = 8 warps (2x4), warp tile 64x32.
// Term-major mma issue.
// modep==0: z in [0,3) -> A=g_X, B=W[z], epilogue Q/K/V;
//           z==3      -> MASK-PACK slice (memory-bound, fills GEMM slack).
// modep==3: A=g_O, B=Wo -> fp32 Yext.
// ---------------------------------------------------------------------------
#define LDU 20                 // smem row stride (uints), conflict-free ldmatrix
#define ASZ (128*LDU)          // one operand tile (uints)
#define GSTG 2                 // pipeline stages (80KB -> 2 CTAs/SM)
#define GNIT (KU_/16)          // 32 mainloop iters

__global__ __launch_bounds__(256, 2) void gemm_bf16(float* __restrict__ Yext,
                                                    int modep,
                                                    const int* __restrict__ maskp)
{
    extern __shared__ __align__(16) uint32_t dsm[];   // GSTG stages x 4 tiles

    int z = blockIdx.z;

    // ---- mask-packing slice (z==3 of the QKV launch) ----
    if (modep == 0 && z == 3) {
        int cta  = blockIdx.y * 8 + blockIdx.x;        // 0..255
        int wrp  = cta * 8 + (threadIdx.x >> 5);       // 0..2047
        int lane = threadIdx.x & 31;
        // B_*S_*WPR = 262144 words = 2048 warps x 128; coarsen x4
        #pragma unroll
        for (int k = 0; k < 32; k++) {
            int w0 = wrp + (4 * k    ) * 2048;
            int w1 = wrp + (4 * k + 1) * 2048;
            int w2 = wrp + (4 * k + 2) * 2048;
            int w3 = wrp + (4 * k + 3) * 2048;
            int v0 = maskp[(size_t)w0 * 32 + lane];
            int v1 = maskp[(size_t)w1 * 32 + lane];
            int v2 = maskp[(size_t)w2 * 32 + lane];
            int v3 = maskp[(size_t)w3 * 32 + lane];
            uint32_t b0 = __ballot_sync(0xffffffffu, v0 != 0);
            uint32_t b1 = __ballot_sync(0xffffffffu, v1 != 0);
            uint32_t b2 = __ballot_sync(0xffffffffu, v2 != 0);
            uint32_t b3 = __ballot_sync(0xffffffffu, v3 != 0);
            if (lane == 0) {
                g_mbits[w0] = b0; g_mbits[w1] = b1;
                g_mbits[w2] = b2; g_mbits[w3] = b3;
            }
        }
        return;
    }

    int outmode = (modep == 3) ? 3 : z;

    const uint32_t *Ah, *Al, *Bh, *Bl;
    if (modep == 3) {
        Ah = g_Oh; Al = g_Ol;
        Bh = g_Wh + (size_t)3 * WSZ; Bl = g_Wl + (size_t)3 * WSZ;
    } else {
        Ah = g_Xh; Al = g_Xl;
        Bh = g_Wh + (size_t)z * WSZ; Bl = g_Wl + (size_t)z * WSZ;
    }

    int t = threadIdx.x, wid = t >> 5, lane = t & 31;
    int wm = wid >> 2, wn = wid & 3;
    int m0 = blockIdx.y << 7, n0 = blockIdx.x << 7;

    int lr  = t >> 1;            // 0..127
    int lcu = (t & 1) << 3;      // 0 or 8

    const uint32_t* pAh = Ah + (size_t)(m0 + lr) * KU_ + lcu;
    const uint32_t* pAl = Al + (size_t)(m0 + lr) * KU_ + lcu;
    const uint32_t* pBh = Bh + (size_t)(n0 + lr) * KU_ + lcu;
    const uint32_t* pBl = Bl + (size_t)(n0 + lr) * KU_ + lcu;

    uint32_t sbase = (uint32_t)__cvta_generic_to_shared(dsm);
    uint32_t dst0  = sbase + (uint32_t)(lr * LDU + lcu) * 4u;

    auto issue = [&](int buf, int ku) {
        uint32_t d = dst0 + (uint32_t)(buf * 4 * ASZ) * 4u;
        cp16(d,                  pAh + ku);
        cp16(d + 16,             pAh + ku + 4);
        cp16(d + ASZ*4,          pAl + ku);
        cp16(d + ASZ*4 + 16,     pAl + ku + 4);
        cp16(d + 2*ASZ*4,        pBh + ku);
        cp16(d + 2*ASZ*4 + 16,   pBh + ku + 4);
        cp16(d + 3*ASZ*4,        pBl + ku);
        cp16(d + 3*ASZ*4 + 16,   pBl + ku + 4);
    };

    float acc[4][4][4];
    #pragma unroll
    for (int i = 0; i < 4; i++)
        #pragma unroll
        for (int j = 0; j < 4; j++)
            #pragma unroll
            for (int q = 0; q < 4; q++) acc[i][j][q] = 0.f;

    int a_row = (lane & 15);
    int a_col = (lane >> 4) << 2;
    int b_row = ((lane >> 4) << 3) + (lane & 7);
    int b_col = ((lane >> 3) & 1) << 2;

    issue(0, 0); CP_COMMIT();

    for (int it = 0; it < GNIT; it++) {
        cp_wait<0>();
        __syncthreads();
        if (it + 1 < GNIT) { issue((it + 1) & 1, (it + 1) * 16); CP_COMMIT(); }

        const uint32_t* bAh = dsm + (it & 1) * 4 * ASZ;
        const uint32_t* bAl = bAh + ASZ;
        const uint32_t* bBh = bAh + 2 * ASZ;
        const uint32_t* bBl = bAh + 3 * ASZ;

        #pragma unroll
        for (int ch = 0; ch < 2; ch++) {
            int kc = ch << 3;
            uint32_t ah[4][4], al[4][4], bh[4][2], bl[4][2];

            #pragma unroll
            for (int mt = 0; mt < 4; mt++) {
                int off = ((wm << 6) + (mt << 4) + a_row) * LDU + kc + a_col;
                uint32_t addr_h = (uint32_t)__cvta_generic_to_shared(&bAh[off]);
                uint32_t addr_l = (uint32_t)__cvta_generic_to_shared(&bAl[off]);
                ldm4(ah[mt][0], ah[mt][1], ah[mt][2], ah[mt][3], addr_h);
                ldm4(al[mt][0], al[mt][1], al[mt][2], al[mt][3], addr_l);
            }
            #pragma unroll
            for (int np = 0; np < 2; np++) {
                int off = ((wn << 5) + (np << 4) + b_row) * LDU + kc + b_col;
                uint32_t addr_h = (uint32_t)__cvta_generic_to_shared(&bBh[off]);
                uint32_t addr_l = (uint32_t)__cvta_generic_to_shared(&bBl[off]);
                ldm4(bh[2*np][0], bh[2*np][1], bh[2*np+1][0], bh[2*np+1][1], addr_h);
                ldm4(bl[2*np][0], bl[2*np][1], bl[2*np+1][0], bl[2*np+1][1], addr_l);
            }

            #pragma unroll
            for (int mt = 0; mt < 4; mt++)
                #pragma unroll
                for (int nt = 0; nt < 4; nt++)
                    mma_bf16(acc[mt][nt], al[mt], bh[nt][0], bh[nt][1]);
            #pragma unroll
            for (int mt = 0; mt < 4; mt++)
                #pragma unroll
                for (int nt = 0; nt < 4; nt++)
                    mma_bf16(acc[mt][nt], ah[mt], bl[nt][0], bl[nt][1]);
            #pragma unroll
            for (int mt = 0; mt < 4; mt++)
                #pragma unroll
                for (int nt = 0; nt < 4; nt++)
                    mma_bf16(acc[mt][nt], ah[mt], bh[nt][0], bh[nt][1]);
        }
    }

    int lq = lane >> 2, lk = lane & 3;

    if (outmode == 3) {
        #pragma unroll
        for (int mt = 0; mt < 4; mt++) {
            int r = m0 + (wm << 6) + (mt << 4) + lq;
            #pragma unroll
            for (int nt = 0; nt < 4; nt++) {
                int c = n0 + (wn << 5) + (nt << 3) + (lk << 1);
                *(float2*)&Yext[(size_t)r * D_ + c] =
                    make_float2(acc[mt][nt][0], acc[mt][nt][1]);
                *(float2*)&Yext[(size_t)(r + 8) * D_ + c] =
                    make_float2(acc[mt][nt][2], acc[mt][nt][3]);
            }
        }
    } else {
        uint32_t* dh = (outmode == 0) ? g_Qh : (outmode == 1 ? g_Kh : g_Vh);
        uint32_t* dl = (outmode == 0) ? g_Ql : (outmode == 1 ? g_Kl : g_Vl);
        #pragma unroll
        for (int mt = 0; mt < 4; mt++) {
            int r = m0 + (wm << 6) + (mt << 4) + lq;
            #pragma unroll
            for (int nt = 0; nt < 4; nt++) {
                int c  = n0 + (wn << 5) + (nt << 3) + (lk << 1);
                int h  = c >> 6, hd = c & 63;
                uint32_t hi, lo;
                {
                    int b = r >> 11, s = r & (S_ - 1);
                    size_t idx = ((size_t)(((b << 4) | h) * S_ + s) << 5) + (hd >> 1);
                    pack_hl(acc[mt][nt][0], acc[mt][nt][1], hi, lo);
                    dh[idx] = hi; dl[idx] = lo;
                }
                {
                    int r2 = r + 8;
                    int b = r2 >> 11, s = r2 & (S_ - 1);
                    size_t idx = ((size_t)(((b << 4) | h) * S_ + s) << 5) + (hd >> 1);
                    pack_hl(acc[mt][nt][2], acc[mt][nt][3], hi, lo);
                    dh[idx] = hi; dl[idx] = lo;
                }
            }
        }
    }
}

// ---------------------------------------------------------------------------
// Tensor-core flash attention (bf16x3), cp.async 3-STAGE pipeline, 2 CTAs/SM.
// Fixed-shift softmax (M=16). Masked scores = -1e-9f exact after *0.125.
// (unchanged from R16)
// ---------------------------------------------------------------------------
#define VLDU 36
#define AVSZ (64*VLDU)        // one K/V tile (uints)
#define ASTG 3                // attention pipeline stages
#define FMAX_ 16.0f           // fixed softmax shift

__global__ __launch_bounds__(256, 2) void attn_tc()
{
    extern __shared__ __align__(16) uint32_t asm_[];  // ASTG stages x 4 tiles

    int t = threadIdx.x, w = t >> 5, lane = t & 31;
    int r = lane >> 2, qt = lane & 3;
    int g8 = lane >> 3, l8 = lane & 7;

    int bh = blockIdx.y, b = bh >> 4, h = bh & 15;
    int q0 = blockIdx.x << 7;
    int qw = q0 + (w << 4);

    const uint32_t* Kh = g_Kh + (size_t)bh * S_ * 32;
    const uint32_t* Kl = g_Kl + (size_t)bh * S_ * 32;
    const uint32_t* Vh = g_Vh + (size_t)bh * S_ * 32;
    const uint32_t* Vl = g_Vl + (size_t)bh * S_ * 32;
    const uint32_t* mbase = g_mbits + ((size_t)b * S_ + qw) * WPR;

    int lrow = t >> 2;           // 0..63
    int lcol = (t & 3) << 3;     // 0,8,16,24

    uint32_t sbase = (uint32_t)__cvta_generic_to_shared(asm_);
    uint32_t dst0  = sbase + (uint32_t)(lrow * VLDU + lcol) * 4u;

    auto issue = [&](int buf, int kv0) {
        size_t s0 = (size_t)(kv0 + lrow) * 32 + lcol;
        uint32_t d = dst0 + (uint32_t)(buf * 4 * AVSZ) * 4u;
        cp16(d,                   Kh + s0);
        cp16(d + 16,              Kh + s0 + 4);
        cp16(d + AVSZ*4,          Kl + s0);
        cp16(d + AVSZ*4 + 16,     Kl + s0 + 4);
        cp16(d + 2*AVSZ*4,        Vh + s0);
        cp16(d + 2*AVSZ*4 + 16,   Vh + s0 + 4);
        cp16(d + 3*AVSZ*4,        Vl + s0);
        cp16(d + 3*AVSZ*4 + 16,   Vl + s0 + 4);
    };

    // Q A-fragments (hi/lo) once
    uint32_t qah[4][4], qal[4][4];
    {
        const uint32_t* Qh = g_Qh + ((size_t)bh * S_ + qw) * 32;
        const uint32_t* Ql = g_Ql + ((size_t)bh * S_ + qw) * 32;
        #pragma unroll
        for (int ks = 0; ks < 4; ks++) {
            int i0 = r * 32 + ks * 8 + qt;
            qah[ks][0] = Qh[i0];           qah[ks][1] = Qh[i0 + 256];
            qah[ks][2] = Qh[i0 + 4];       qah[ks][3] = Qh[i0 + 260];
            qal[ks][0] = Ql[i0];           qal[ks][1] = Ql[i0 + 256];
            qal[ks][2] = Ql[i0 + 4];       qal[ks][3] = Ql[i0 + 260];
        }
    }

    float oacc[8][4];
    #pragma unroll
    for (int i = 0; i < 8; i++)
        #pragma unroll
        for (int j = 0; j < 4; j++) oacc[i][j] = 0.f;
    float li0 = 0.f, li1 = 0.f;

    // prologue: stages 0,1
    issue(0, 0);  CP_COMMIT();
    issue(1, 64); CP_COMMIT();

    const int NIT = S_ / 64;     // 32
    for (int it = 0; it < NIT; it++) {
        cp_wait<ASTG - 2>();     // stage `it` resident, one group may remain
        __syncthreads();         // WAR: all warps done with buffer (it+2)%3
        if (it + 2 < NIT) { issue((it + 2) % ASTG, (it + 2) << 6); CP_COMMIT(); }

        const uint32_t* bKh = asm_ + (it % ASTG) * 4 * AVSZ;
        const uint32_t* bKl = bKh + AVSZ;
        const uint32_t* bVh = bKh + 2 * AVSZ;
        const uint32_t* bVl = bKh + 3 * AVSZ;

        float sacc[8][4];
        #pragma unroll
        for (int i = 0; i < 8; i++)
            #pragma unroll
            for (int j = 0; j < 4; j++) sacc[i][j] = 0.f;

        #pragma unroll
        for (int ks = 0; ks < 4; ks++) {
            #pragma unroll
            for (int ntp = 0; ntp < 4; ntp++) {
                int row = (ntp << 4) + ((g8 & 2) ? 8 : 0) + l8;
                int col = (ks << 3) + ((g8 & 1) ? 4 : 0);
                uint32_t ah = (uint32_t)__cvta_generic_to_shared(&bKh[row * VLDU + col]);
                uint32_t al = (uint32_t)__cvta_generic_to_shared(&bKl[row * VLDU + col]);
                uint32_t h0, h1, h2, h3, l0, l1, l2, l3;
                ldm4(h0, h1, h2, h3, ah);
                ldm4(l0, l1, l2, l3, al);
                mma_bf16(sacc[2*ntp],   qal[ks], h0, h1);
                mma_bf16(sacc[2*ntp+1], qal[ks], h2, h3);
                mma_bf16(sacc[2*ntp],   qah[ks], l0, l1);
                mma_bf16(sacc[2*ntp+1], qah[ks], l2, l3);
                mma_bf16(sacc[2*ntp],   qah[ks], h0, h1);
                mma_bf16(sacc[2*ntp+1], qah[ks], h2, h3);
            }
        }

        {
            int kv0 = it << 6;
            const uint32_t* mb = mbase + (kv0 >> 5);
            uint32_t w0a = mb[(size_t)r * WPR];
            uint32_t w0b = mb[(size_t)r * WPR + 1];
            uint32_t w1a = mb[(size_t)(r + 8) * WPR];
            uint32_t w1b = mb[(size_t)(r + 8) * WPR + 1];
            #pragma unroll
            for (int nt = 0; nt < 8; nt++) {
                uint32_t wlo = (nt < 4) ? w0a : w0b;
                uint32_t whi = (nt < 4) ? w1a : w1b;
                int base = ((nt & 3) << 3) + (qt << 1);
                sacc[nt][0] = ((wlo >> base)       & 1) ? sacc[nt][0] * 0.125f : -1e-9f;
                sacc[nt][1] = ((wlo >> (base + 1)) & 1) ? sacc[nt][1] * 0.125f : -1e-9f;
                sacc[nt][2] = ((whi >> base)       & 1) ? sacc[nt][2] * 0.125f : -1e-9f;
                sacc[nt][3] = ((whi >> (base + 1)) & 1) ? sacc[nt][3] * 0.125f : -1e-9f;
            }
        }

        float rs0 = 0.f, rs1 = 0.f;
        #pragma unroll
        for (int nt = 0; nt < 8; nt++) {
            sacc[nt][0] = __expf(sacc[nt][0] - FMAX_);
            sacc[nt][1] = __expf(sacc[nt][1] - FMAX_);
            sacc[nt][2] = __expf(sacc[nt][2] - FMAX_);
            sacc[nt][3] = __expf(sacc[nt][3] - FMAX_);
            rs0 += sacc[nt][0] + sacc[nt][1];
            rs1 += sacc[nt][2] + sacc[nt][3];
        }
        rs0 += __shfl_xor_sync(0xffffffffu, rs0, 1);
        rs0 += __shfl_xor_sync(0xffffffffu, rs0, 2);
        rs1 += __shfl_xor_sync(0xffffffffu, rs1, 1);
        rs1 += __shfl_xor_sync(0xffffffffu, rs1, 2);
        li0 += rs0;
        li1 += rs1;

        uint32_t pah[4][4], pal[4][4];
        #pragma unroll
        for (int ks = 0; ks < 4; ks++) {
            pack_hl(sacc[2*ks][0],   sacc[2*ks][1],   pah[ks][0], pal[ks][0]);
            pack_hl(sacc[2*ks][2],   sacc[2*ks][3],   pah[ks][1], pal[ks][1]);
            pack_hl(sacc[2*ks+1][0], sacc[2*ks+1][1], pah[ks][2], pal[ks][2]);
            pack_hl(sacc[2*ks+1][2], sacc[2*ks+1][3], pah[ks][3], pal[ks][3]);
        }

        #pragma unroll
        for (int ks = 0; ks < 4; ks++) {
            #pragma unroll
            for (int ntp = 0; ntp < 4; ntp++) {
                int row = (ks << 4) + ((g8 & 1) ? 8 : 0) + l8;
                int col = (ntp << 3) + ((g8 & 2) ? 4 : 0);
                uint32_t ah = (uint32_t)__cvta_generic_to_shared(&bVh[row * VLDU + col]);
                uint32_t al = (uint32_t)__cvta_generic_to_shared(&bVl[row * VLDU + col]);
                uint32_t h0, h1, h2, h3, l0, l1, l2, l3;
                ldm4t(h0, h1, h2, h3, ah);
                ldm4t(l0, l1, l2, l3, al);
                mma_bf16(oacc[2*ntp],   pal[ks], h0, h1);
                mma_bf16(oacc[2*ntp+1], pal[ks], h2, h3);
                mma_bf16(oacc[2*ntp],   pah[ks], l0, l1);
                mma_bf16(oacc[2*ntp+1], pah[ks], l2, l3);
                mma_bf16(oacc[2*ntp],   pah[ks], h0, h1);
                mma_bf16(oacc[2*ntp+1], pah[ks], h2, h3);
            }
        }
    }

    // epilogue: normalize, pack to bf16 hi/lo O [m][d/2]
    float inv0 = 1.0f / li0, inv1 = 1.0f / li1;
    size_t rowbase = (size_t)b * S_ + qw;
    uint32_t* Oh = g_Oh + rowbase * KU_ + (h << 5);
    uint32_t* Ol = g_Ol + rowbase * KU_ + (h << 5);
    #pragma unroll
    for (int nt = 0; nt < 8; nt++) {
        int cu = (nt << 2) + qt;
        uint32_t hi, lo;
        pack_hl(oacc[nt][0] * inv0, oacc[nt][1] * inv0, hi, lo);
        Oh[(size_t)r * KU_ + cu] = hi;
        Ol[(size_t)r * KU_ + cu] = lo;
        pack_hl(oacc[nt][2] * inv1, oacc[nt][3] * inv1, hi, lo);
        Oh[(size_t)(r + 8) * KU_ + cu] = hi;
        Ol[(size_t)(r + 8) * KU_ + cu] = lo;
    }
}

// ---------------------------------------------------------------------------
extern "C" void kernel_launch(void* const* d_in, const int* in_sizes, int n_in,
                              void* d_out, int out_size)
{
    const float* X    = (const float*)d_in[0];
    const int*   mask = (const int*)d_in[1];
    const float* Wq   = (const float*)d_in[2];
    const float* Wk   = (const float*)d_in[3];
    const float* Wv   = (const float*)d_in[4];
    const float* Wo   = (const float*)d_in[5];
    float* out = (float*)d_out;

    size_t gsmem  = (size_t)GSTG * 4 * ASZ * sizeof(uint32_t);    // 81920 B
    size_t atsmem = (size_t)ASTG * 4 * AVSZ * sizeof(uint32_t);   // 110592 B
    cudaFuncSetAttribute(gemm_bf16,
                         cudaFuncAttributeMaxDynamicSharedMemorySize, (int)gsmem);
    cudaFuncSetAttribute(attn_tc,
                         cudaFuncAttributeMaxDynamicSharedMemorySize, (int)atsmem);

    prep_xw<<<2048, 256>>>(X, Wq, Wk, Wv, Wo);

    // z slices 0..2 = Q/K/V projections; z slice 3 = mask bit-packing
    gemm_bf16<<<dim3(D_/128, M_/128, 4), 256, gsmem>>>(nullptr, 0, mask);
    attn_tc<<<dim3(S_ / 128, B_ * H_), 256, atsmem>>>();
    gemm_bf16<<<dim3(D_/128, M_/128, 1), 256, gsmem>>>(out, 3, mask);
}